// round 3
// baseline (speedup 1.0000x reference)
#include <cuda_runtime.h>

// Problem constants (fixed by setup_inputs)
static constexpr int N_NODES = 100000;
static constexpr int N_EDGES = 1600000;
static constexpr int SCAN_B  = 512;
static constexpr int SCAN_NB = (N_NODES + SCAN_B - 1) / SCAN_B;  // 196

// ---------------- scratch (static __device__, allocation-free) ----------------
__device__ int   g_cnt[N_NODES];        // degree counts, then CSR fill cursor
__device__ int   g_row[N_NODES + 1];    // CSR row offsets
__device__ int   g_bsum[256];
__device__ int   g_boff[256];
__device__ int   g_col[N_EDGES];        // CSR: src node per entry
__device__ float g_wsrc[N_EDGES];       // CSR: dinv[src] per entry
__device__ float g_dinv[N_NODES];
__device__ float g_t1[N_NODES * 16];    // x @ W1
__device__ float g_h1[N_NODES * 16];    // relu(agg(t1)+b1)
__device__ float g_a2[N_NODES * 16];    // agg(h1)
__device__ float g_h2[N_NODES * 64];    // relu(a2@W2+b2)
__device__ float g_a3[N_NODES * 64];    // agg(h2)
__device__ int   g_is64;

// ---------------- dtype detection (int64 vs int32 edge_index) ----------------
__global__ void k_detect(const unsigned int* __restrict__ e) {
    if (threadIdx.x == 0) {
        int is64 = 1;
        for (int i = 0; i < 64; i++) {
            if (e[2 * i + 1] != 0u) { is64 = 0; break; }
        }
        g_is64 = is64;
    }
}

__device__ __forceinline__ void edge_sd(const void* e, int idx, int& s, int& d) {
    if (g_is64) {
        const long long* p = (const long long*)e;
        s = (int)p[idx];
        d = (int)p[N_EDGES + idx];
    } else {
        const int* p = (const int*)e;
        s = p[idx];
        d = p[N_EDGES + idx];
    }
}

// ---------------- graph build ----------------
__global__ void k_init() {
    int i = blockIdx.x * blockDim.x + threadIdx.x;
    if (i < N_NODES) g_cnt[i] = 0;
}

__global__ void k_count(const void* e) {
    int i = blockIdx.x * blockDim.x + threadIdx.x;
    if (i >= N_EDGES) return;
    int s, d;
    edge_sd(e, i, s, d);
    if ((unsigned)d >= (unsigned)N_NODES) return;   // safety net
    atomicAdd(&g_cnt[d], 1);
}

__global__ void k_dinv() {
    int i = blockIdx.x * blockDim.x + threadIdx.x;
    if (i < N_NODES) g_dinv[i] = rsqrtf((float)(g_cnt[i] + 1));  // +1 self loop
}

__global__ void k_scanA() {
    __shared__ int s[SCAN_B];
    int i = blockIdx.x * SCAN_B + threadIdx.x;
    int v = (i < N_NODES) ? g_cnt[i] : 0;
    s[threadIdx.x] = v;
    __syncthreads();
    for (int d = 1; d < SCAN_B; d <<= 1) {
        int t = (threadIdx.x >= d) ? s[threadIdx.x - d] : 0;
        __syncthreads();
        s[threadIdx.x] += t;
        __syncthreads();
    }
    if (i < N_NODES) g_row[i] = s[threadIdx.x] - v;   // block-local exclusive
    if (threadIdx.x == SCAN_B - 1) g_bsum[blockIdx.x] = s[threadIdx.x];
}

__global__ void k_scanB() {
    __shared__ int s[256];
    int v = (threadIdx.x < SCAN_NB) ? g_bsum[threadIdx.x] : 0;
    s[threadIdx.x] = v;
    __syncthreads();
    for (int d = 1; d < 256; d <<= 1) {
        int t = (threadIdx.x >= d) ? s[threadIdx.x - d] : 0;
        __syncthreads();
        s[threadIdx.x] += t;
        __syncthreads();
    }
    g_boff[threadIdx.x] = s[threadIdx.x] - v;  // exclusive block offsets
}

__global__ void k_scanC() {
    int i = blockIdx.x * blockDim.x + threadIdx.x;
    if (i < N_NODES) {
        g_row[i] += g_boff[i / SCAN_B];
        g_cnt[i] = 0;   // reset as fill cursor
    }
    if (i == 0) g_row[N_NODES] = N_EDGES;
}

__global__ void k_fill(const void* e) {
    int i = blockIdx.x * blockDim.x + threadIdx.x;
    if (i >= N_EDGES) return;
    int s, d;
    edge_sd(e, i, s, d);
    if ((unsigned)d >= (unsigned)N_NODES || (unsigned)s >= (unsigned)N_NODES) return;
    int pos = atomicAdd(&g_cnt[d], 1);
    int idx = g_row[d] + pos;
    if (idx < N_EDGES) {
        g_col[idx]  = s;
        g_wsrc[idx] = g_dinv[s];
    }
}

// ---------------- layer 1 GEMM: t1 = x @ W1  (N,128)x(128,16) ----------------
__global__ void __launch_bounds__(256) k_gemm1(const float* __restrict__ x,
                                               const float* __restrict__ W1) {
    __shared__ float sW[128 * 16];
    for (int idx = threadIdx.x; idx < 128 * 16; idx += 256) sW[idx] = W1[idx];
    __syncthreads();
    int tid = blockIdx.x * 256 + threadIdx.x;
    if (tid >= N_NODES * 16) return;
    int n = tid >> 4, f = tid & 15;
    const float4* xr = (const float4*)(x + (size_t)n * 128);
    float acc = 0.f;
#pragma unroll
    for (int k4 = 0; k4 < 32; k4++) {
        float4 v = __ldg(&xr[k4]);
        acc = fmaf(v.x, sW[(4 * k4 + 0) * 16 + f], acc);
        acc = fmaf(v.y, sW[(4 * k4 + 1) * 16 + f], acc);
        acc = fmaf(v.z, sW[(4 * k4 + 2) * 16 + f], acc);
        acc = fmaf(v.w, sW[(4 * k4 + 3) * 16 + f], acc);
    }
    g_t1[tid] = acc;
}

// ---------------- normalized aggregation over CSR ----------------
// o[i,f] = dinv[i] * ( sum_e dinv[src_e]*t[src_e,f]  +  dinv[i]*t[i,f] )  [+bias, relu]
// SEL chooses in/out arrays INSIDE device code (cannot pass __device__ symbols
// from host: on GB300 the host shadow address is ATS-valid and reads zeros!)
template <int F, int SEL, bool RB>
__global__ void __launch_bounds__(256) k_agg(const float* __restrict__ bias) {
    const float* __restrict__ t;
    float* __restrict__ o;
    if (SEL == 0)      { t = g_t1; o = g_h1; }
    else if (SEL == 1) { t = g_h1; o = g_a2; }
    else               { t = g_h2; o = g_a3; }

    constexpr int GP = 256 / F;
    int f = threadIdx.x % F;
    int i = blockIdx.x * GP + threadIdx.x / F;
    if (i >= N_NODES) return;
    float di  = g_dinv[i];
    float acc = di * t[i * F + f];                 // self loop (outer di applied later)
    int beg = g_row[i], end = g_row[i + 1];
    for (int j = beg; j < end; ++j) {
        int   s = __ldg(&g_col[j]);
        float w = __ldg(&g_wsrc[j]);
        acc = fmaf(w, __ldg(&t[s * F + f]), acc);
    }
    acc *= di;
    if (RB) acc = fmaxf(acc + bias[f], 0.0f);
    o[i * F + f] = acc;
}

// ---------------- layer 2 GEMM: h2 = relu(a2 @ W2 + b2)  (N,16)x(16,64) ----------------
__global__ void __launch_bounds__(256) k_gemm2(const float* __restrict__ W2,
                                               const float* __restrict__ b2) {
    __shared__ float sW[16 * 64];
    for (int idx = threadIdx.x; idx < 16 * 64; idx += 256) sW[idx] = W2[idx];
    __syncthreads();
    int tid = blockIdx.x * 256 + threadIdx.x;
    if (tid >= N_NODES * 64) return;
    int n = tid >> 6, f = tid & 63;
    const float4* ar = (const float4*)(g_a2 + n * 16);
    float acc = b2[f];
#pragma unroll
    for (int k4 = 0; k4 < 4; k4++) {
        float4 v = __ldg(&ar[k4]);
        acc = fmaf(v.x, sW[(4 * k4 + 0) * 64 + f], acc);
        acc = fmaf(v.y, sW[(4 * k4 + 1) * 64 + f], acc);
        acc = fmaf(v.z, sW[(4 * k4 + 2) * 64 + f], acc);
        acc = fmaf(v.w, sW[(4 * k4 + 3) * 64 + f], acc);
    }
    g_h2[tid] = fmaxf(acc, 0.f);
}

// ---------------- fused layer 3 + FC:
// out[n] = sum_j relu( a3[n,:] . W3[:,j] + b3[j] ) * Wfc[j] + bfc
__global__ void __launch_bounds__(256) k_final(const float* __restrict__ W3,
                                               const float* __restrict__ b3,
                                               const float* __restrict__ Wfc,
                                               const float* __restrict__ bfc,
                                               float* __restrict__ out) {
    __shared__ float sW[64 * 128];   // 32KB
    __shared__ float sB[128];
    __shared__ float sF[128];
    for (int idx = threadIdx.x; idx < 64 * 128; idx += 256) sW[idx] = W3[idx];
    if (threadIdx.x < 128) {
        sB[threadIdx.x] = b3[threadIdx.x];
        sF[threadIdx.x] = Wfc[threadIdx.x];
    }
    __syncthreads();
    int n = blockIdx.x * 256 + threadIdx.x;
    if (n >= N_NODES) return;

    float a[64];
    const float4* ar = (const float4*)(g_a3 + (size_t)n * 64);
#pragma unroll
    for (int k4 = 0; k4 < 16; k4++) {
        float4 v = __ldg(&ar[k4]);
        a[4 * k4 + 0] = v.x; a[4 * k4 + 1] = v.y;
        a[4 * k4 + 2] = v.z; a[4 * k4 + 3] = v.w;
    }

    float o = 0.f;
#pragma unroll 1
    for (int j = 0; j < 128; j += 4) {
        float s0 = sB[j], s1 = sB[j + 1], s2 = sB[j + 2], s3 = sB[j + 3];
#pragma unroll
        for (int k = 0; k < 64; k++) {
            float av = a[k];
            s0 = fmaf(av, sW[k * 128 + j + 0], s0);
            s1 = fmaf(av, sW[k * 128 + j + 1], s1);
            s2 = fmaf(av, sW[k * 128 + j + 2], s2);
            s3 = fmaf(av, sW[k * 128 + j + 3], s3);
        }
        o += fmaxf(s0, 0.f) * sF[j + 0] + fmaxf(s1, 0.f) * sF[j + 1] +
             fmaxf(s2, 0.f) * sF[j + 2] + fmaxf(s3, 0.f) * sF[j + 3];
    }
    out[n] = o + bfc[0];
}

// ---------------- launch ----------------
extern "C" void kernel_launch(void* const* d_in, const int* in_sizes, int n_in,
                              void* d_out, int out_size) {
    const float* x   = (const float*)d_in[0];
    const void*  ei  = d_in[1];
    const float* W1  = (const float*)d_in[2];
    const float* b1  = (const float*)d_in[3];
    const float* W2  = (const float*)d_in[4];
    const float* b2  = (const float*)d_in[5];
    const float* W3  = (const float*)d_in[6];
    const float* b3  = (const float*)d_in[7];
    const float* Wfc = (const float*)d_in[8];
    const float* bfc = (const float*)d_in[9];
    float* out = (float*)d_out;

    const int TB = 256;
    const int gN  = (N_NODES + TB - 1) / TB;
    const int gE  = (N_EDGES + TB - 1) / TB;

    // graph construction
    k_detect<<<1, 32>>>((const unsigned int*)ei);
    k_init<<<gN, TB>>>();
    k_count<<<gE, TB>>>(ei);
    k_dinv<<<gN, TB>>>();
    k_scanA<<<SCAN_NB, SCAN_B>>>();
    k_scanB<<<1, 256>>>();
    k_scanC<<<gN, TB>>>();
    k_fill<<<gE, TB>>>(ei);

    // layer 1: GEMM first (128->16), then aggregate 16-wide (+b1+relu)
    k_gemm1<<<(N_NODES * 16 + TB - 1) / TB, TB>>>(x, W1);
    k_agg<16, 0, true><<<(N_NODES * 16 + TB - 1) / TB, TB>>>(b1);

    // layer 2: aggregate first (16-wide), then GEMM 16->64 (+bias+relu)
    k_agg<16, 1, false><<<(N_NODES * 16 + TB - 1) / TB, TB>>>(nullptr);
    k_gemm2<<<(N_NODES * 64 + TB - 1) / TB, TB>>>(W2, b2);

    // layer 3: aggregate first (64-wide), then fused GEMM 64->128 + relu + FC
    k_agg<64, 2, false><<<(N_NODES * 64 + TB - 1) / TB, TB>>>(nullptr);
    k_final<<<(N_NODES + TB - 1) / TB, TB>>>(W3, b3, Wfc, bfc, out);
}

// round 4
// speedup vs baseline: 1.3226x; 1.3226x over previous
#include <cuda_runtime.h>

// Problem constants (fixed by setup_inputs)
static constexpr int N_NODES = 100000;
static constexpr int N_EDGES = 1600000;
static constexpr int SCAN_B  = 512;
static constexpr int SCAN_NB = (N_NODES + SCAN_B - 1) / SCAN_B;  // 196

// ---------------- scratch (static __device__, allocation-free) ----------------
__device__ int   g_cnt[N_NODES];        // degree counts, then CSR fill cursor
__device__ int   g_row[N_NODES + 1];    // CSR row offsets
__device__ int   g_bsum[256];
__device__ int   g_boff[256];
__device__ int   g_col[N_EDGES];        // CSR: src node per entry
__device__ float g_dinv[N_NODES];
__device__ float g_t1[N_NODES * 16];    // dinv * (x @ W1)
__device__ float g_h1[N_NODES * 16];    // dinv * relu(agg + b1)   (pre-scaled)
__device__ float g_a2[N_NODES * 16];    // dinv * sum              (plain agg out)
__device__ float g_h2[N_NODES * 64];    // dinv * relu(a2@W2+b2)   (pre-scaled)
__device__ float g_a3[N_NODES * 64];    // dinv * sum
__device__ int   g_is64;

// ---------------- f32x2 packed-FMA helpers (sm_103a) ----------------
__device__ __forceinline__ unsigned long long pack2(float v) {
    unsigned long long r;
    asm("mov.b64 %0, {%1, %1};" : "=l"(r) : "f"(v));
    return r;
}
__device__ __forceinline__ void ffma2(unsigned long long& d, unsigned long long a,
                                      unsigned long long b) {
    asm("fma.rn.f32x2 %0, %1, %2, %0;" : "+l"(d) : "l"(a), "l"(b));
}
__device__ __forceinline__ float2 unpack2(unsigned long long v) {
    float2 r;
    asm("mov.b64 {%0, %1}, %2;" : "=f"(r.x), "=f"(r.y) : "l"(v));
    return r;
}

// ---------------- edge decode ----------------
__device__ __forceinline__ void edge_sd(const void* e, int idx, int& s, int& d) {
    if (g_is64) {
        const long long* p = (const long long*)e;
        s = (int)p[idx];
        d = (int)p[N_EDGES + idx];
    } else {
        const int* p = (const int*)e;
        s = p[idx];
        d = p[N_EDGES + idx];
    }
}

// ---------------- graph build ----------------
// init counters + dtype detect (int64 edge_index has all-zero high words)
__global__ void k_init(const unsigned int* __restrict__ e) {
    int i = blockIdx.x * blockDim.x + threadIdx.x;
    if (i < N_NODES) g_cnt[i] = 0;
    if (i == 0) {
        int is64 = 1;
        for (int k = 0; k < 64; k++) {
            if (e[2 * k + 1] != 0u) { is64 = 0; break; }
        }
        g_is64 = is64;
    }
}

__global__ void k_count(const void* e) {
    int i = blockIdx.x * blockDim.x + threadIdx.x;
    if (i >= N_EDGES) return;
    int d;
    if (g_is64) d = (int)((const long long*)e)[N_EDGES + i];
    else        d = ((const int*)e)[N_EDGES + i];
    if ((unsigned)d >= (unsigned)N_NODES) return;
    atomicAdd(&g_cnt[d], 1);
}

// block-local exclusive scan of counts; also computes dinv = rsqrt(deg+1)
__global__ void k_scanA() {
    __shared__ int s[SCAN_B];
    int i = blockIdx.x * SCAN_B + threadIdx.x;
    int v = (i < N_NODES) ? g_cnt[i] : 0;
    if (i < N_NODES) g_dinv[i] = rsqrtf((float)(v + 1));
    s[threadIdx.x] = v;
    __syncthreads();
    for (int d = 1; d < SCAN_B; d <<= 1) {
        int t = (threadIdx.x >= d) ? s[threadIdx.x - d] : 0;
        __syncthreads();
        s[threadIdx.x] += t;
        __syncthreads();
    }
    if (i < N_NODES) g_row[i] = s[threadIdx.x] - v;
    if (threadIdx.x == SCAN_B - 1) g_bsum[blockIdx.x] = s[threadIdx.x];
}

__global__ void k_scanB() {
    __shared__ int s[256];
    int v = (threadIdx.x < SCAN_NB) ? g_bsum[threadIdx.x] : 0;
    s[threadIdx.x] = v;
    __syncthreads();
    for (int d = 1; d < 256; d <<= 1) {
        int t = (threadIdx.x >= d) ? s[threadIdx.x - d] : 0;
        __syncthreads();
        s[threadIdx.x] += t;
        __syncthreads();
    }
    g_boff[threadIdx.x] = s[threadIdx.x] - v;
}

__global__ void k_scanC() {
    int i = blockIdx.x * blockDim.x + threadIdx.x;
    if (i < N_NODES) {
        g_row[i] += g_boff[i / SCAN_B];
        g_cnt[i] = 0;   // reset as fill cursor
    }
    if (i == 0) g_row[N_NODES] = N_EDGES;
}

__global__ void k_fill(const void* e) {
    int i = blockIdx.x * blockDim.x + threadIdx.x;
    if (i >= N_EDGES) return;
    int s, d;
    edge_sd(e, i, s, d);
    if ((unsigned)d >= (unsigned)N_NODES || (unsigned)s >= (unsigned)N_NODES) return;
    int pos = atomicAdd(&g_cnt[d], 1);
    int idx = g_row[d] + pos;
    if (idx < N_EDGES) g_col[idx] = s;
}

// ---------------- layer 1 GEMM: t1' = dinv ⊙ (x @ W1)  (N,128)x(128,16) -------
// node-per-thread, 16 accumulators, LDS.128 weight rows (broadcast across warp)
__global__ void __launch_bounds__(256) k_gemm1(const float* __restrict__ x,
                                               const float* __restrict__ W1) {
    __shared__ __align__(16) float sW[128 * 16];
    for (int idx = threadIdx.x; idx < 128 * 16; idx += 256) sW[idx] = W1[idx];
    __syncthreads();
    int n = blockIdx.x * 256 + threadIdx.x;
    if (n >= N_NODES) return;
    const float4* xr = (const float4*)(x + (size_t)n * 128);
    float acc[16];
#pragma unroll
    for (int q = 0; q < 16; q++) acc[q] = 0.f;
#pragma unroll 4
    for (int k4 = 0; k4 < 32; k4++) {
        float4 v = __ldg(&xr[k4]);
#pragma unroll
        for (int kk = 0; kk < 4; kk++) {
            float xv = (kk == 0) ? v.x : (kk == 1) ? v.y : (kk == 2) ? v.z : v.w;
            const float4* wr = (const float4*)(sW + (4 * k4 + kk) * 16);
            float4 w0 = wr[0], w1 = wr[1], w2 = wr[2], w3 = wr[3];
            acc[0]  = fmaf(xv, w0.x, acc[0]);  acc[1]  = fmaf(xv, w0.y, acc[1]);
            acc[2]  = fmaf(xv, w0.z, acc[2]);  acc[3]  = fmaf(xv, w0.w, acc[3]);
            acc[4]  = fmaf(xv, w1.x, acc[4]);  acc[5]  = fmaf(xv, w1.y, acc[5]);
            acc[6]  = fmaf(xv, w1.z, acc[6]);  acc[7]  = fmaf(xv, w1.w, acc[7]);
            acc[8]  = fmaf(xv, w2.x, acc[8]);  acc[9]  = fmaf(xv, w2.y, acc[9]);
            acc[10] = fmaf(xv, w2.z, acc[10]); acc[11] = fmaf(xv, w2.w, acc[11]);
            acc[12] = fmaf(xv, w3.x, acc[12]); acc[13] = fmaf(xv, w3.y, acc[13]);
            acc[14] = fmaf(xv, w3.z, acc[14]); acc[15] = fmaf(xv, w3.w, acc[15]);
        }
    }
    float di = g_dinv[n];
    float4* o = (float4*)(g_t1 + (size_t)n * 16);
#pragma unroll
    for (int q = 0; q < 4; q++)
        o[q] = make_float4(di * acc[4 * q], di * acc[4 * q + 1],
                           di * acc[4 * q + 2], di * acc[4 * q + 3]);
}

// ---------------- aggregation over CSR (inputs pre-scaled by dinv) -------------
// S[i] = t'[i] + Σ_j t'[col[j]]       (no per-edge weight — it's baked into t')
// SEL 0: h1' = relu(di²·S + di·b1)    (scaled for next agg)
// SEL 1: a2  = di·S
// SEL 2: a3  = di·S
template <int F, int SEL>
__global__ void __launch_bounds__(256) k_aggv(const float* __restrict__ bias) {
    constexpr int G = F / 4;             // float4 lanes per node
    constexpr int NPB = 256 / G;
    const float4* __restrict__ t4;
    float4* __restrict__ o4;
    if (SEL == 0)      { t4 = (const float4*)g_t1; o4 = (float4*)g_h1; }
    else if (SEL == 1) { t4 = (const float4*)g_h1; o4 = (float4*)g_a2; }
    else               { t4 = (const float4*)g_h2; o4 = (float4*)g_a3; }

    int g = threadIdx.x & (G - 1);
    int i = blockIdx.x * NPB + (threadIdx.x / G);
    if (i >= N_NODES) return;

    float4 acc = t4[(size_t)i * G + g];  // self loop term
    int beg = g_row[i], end = g_row[i + 1];
    int j = beg;
    for (; j + 3 < end; j += 4) {
        int s0 = __ldg(&g_col[j]);
        int s1 = __ldg(&g_col[j + 1]);
        int s2 = __ldg(&g_col[j + 2]);
        int s3 = __ldg(&g_col[j + 3]);
        float4 v0 = __ldg(&t4[(size_t)s0 * G + g]);
        float4 v1 = __ldg(&t4[(size_t)s1 * G + g]);
        float4 v2 = __ldg(&t4[(size_t)s2 * G + g]);
        float4 v3 = __ldg(&t4[(size_t)s3 * G + g]);
        acc.x += (v0.x + v1.x) + (v2.x + v3.x);
        acc.y += (v0.y + v1.y) + (v2.y + v3.y);
        acc.z += (v0.z + v1.z) + (v2.z + v3.z);
        acc.w += (v0.w + v1.w) + (v2.w + v3.w);
    }
    for (; j < end; j++) {
        int s = __ldg(&g_col[j]);
        float4 v = __ldg(&t4[(size_t)s * G + g]);
        acc.x += v.x; acc.y += v.y; acc.z += v.z; acc.w += v.w;
    }
    float di = g_dinv[i];
    float4 r;
    if (SEL == 0) {
        float4 b = ((const float4*)bias)[g];
        float d2 = di * di;
        r.x = fmaxf(fmaf(d2, acc.x, di * b.x), 0.f);
        r.y = fmaxf(fmaf(d2, acc.y, di * b.y), 0.f);
        r.z = fmaxf(fmaf(d2, acc.z, di * b.z), 0.f);
        r.w = fmaxf(fmaf(d2, acc.w, di * b.w), 0.f);
    } else {
        r = make_float4(di * acc.x, di * acc.y, di * acc.z, di * acc.w);
    }
    o4[(size_t)i * G + g] = r;
}

// ---------------- layer 2 GEMM: h2' = dinv ⊙ relu(a2 @ W2 + b2)  (16->64) ------
__global__ void __launch_bounds__(256) k_gemm2(const float* __restrict__ W2,
                                               const float* __restrict__ b2) {
    __shared__ __align__(16) float sW[16 * 64];
    for (int idx = threadIdx.x; idx < 16 * 64; idx += 256) sW[idx] = W2[idx];
    __syncthreads();
    int tid = blockIdx.x * 256 + threadIdx.x;
    if (tid >= N_NODES * 64) return;
    int n = tid >> 6, f = tid & 63;
    const float4* ar = (const float4*)(g_a2 + (size_t)n * 16);
    float acc = b2[f];
#pragma unroll
    for (int k4 = 0; k4 < 4; k4++) {
        float4 v = __ldg(&ar[k4]);
        acc = fmaf(v.x, sW[(4 * k4 + 0) * 64 + f], acc);
        acc = fmaf(v.y, sW[(4 * k4 + 1) * 64 + f], acc);
        acc = fmaf(v.z, sW[(4 * k4 + 2) * 64 + f], acc);
        acc = fmaf(v.w, sW[(4 * k4 + 3) * 64 + f], acc);
    }
    float di = g_dinv[n];
    g_h2[tid] = fmaxf(di * acc, 0.f);   // relu(di*x) == di*relu(x), di>0
}

// ---------------- fused layer 3 + FC (f32x2 packed FFMA):
// out[n] = Σ_j relu( a3[n,:]·W3[:,j] + b3[j] ) * Wfc[j] + bfc
__global__ void __launch_bounds__(256) k_final(const float* __restrict__ W3,
                                               const float* __restrict__ b3,
                                               const float* __restrict__ Wfc,
                                               const float* __restrict__ bfc,
                                               float* __restrict__ out) {
    __shared__ __align__(16) float sW[64 * 128];   // 32KB
    __shared__ __align__(16) float sB[128];
    __shared__ __align__(16) float sF[128];
    for (int idx = threadIdx.x; idx < 64 * 128; idx += 256) sW[idx] = W3[idx];
    if (threadIdx.x < 128) {
        sB[threadIdx.x] = b3[threadIdx.x];
        sF[threadIdx.x] = Wfc[threadIdx.x];
    }
    __syncthreads();
    int n = blockIdx.x * 256 + threadIdx.x;
    if (n >= N_NODES) return;

    float a[64];
    const float4* ar = (const float4*)(g_a3 + (size_t)n * 64);
#pragma unroll
    for (int k4 = 0; k4 < 16; k4++) {
        float4 v = __ldg(&ar[k4]);
        a[4 * k4 + 0] = v.x; a[4 * k4 + 1] = v.y;
        a[4 * k4 + 2] = v.z; a[4 * k4 + 3] = v.w;
    }

    float o = 0.f;
#pragma unroll 1
    for (int j = 0; j < 128; j += 8) {
        const ulonglong2* bi = (const ulonglong2*)(sB + j);
        ulonglong2 b01 = bi[0], b23 = bi[1];
        unsigned long long acc0 = b01.x, acc1 = b01.y;
        unsigned long long acc2 = b23.x, acc3 = b23.y;
#pragma unroll
        for (int k = 0; k < 64; k++) {
            unsigned long long av = pack2(a[k]);
            const ulonglong2* w = (const ulonglong2*)(sW + k * 128 + j);
            ulonglong2 w01 = w[0], w23 = w[1];
            ffma2(acc0, av, w01.x);
            ffma2(acc1, av, w01.y);
            ffma2(acc2, av, w23.x);
            ffma2(acc3, av, w23.y);
        }
        float2 p0 = unpack2(acc0), p1 = unpack2(acc1);
        float2 p2 = unpack2(acc2), p3 = unpack2(acc3);
        o += fmaxf(p0.x, 0.f) * sF[j + 0] + fmaxf(p0.y, 0.f) * sF[j + 1];
        o += fmaxf(p1.x, 0.f) * sF[j + 2] + fmaxf(p1.y, 0.f) * sF[j + 3];
        o += fmaxf(p2.x, 0.f) * sF[j + 4] + fmaxf(p2.y, 0.f) * sF[j + 5];
        o += fmaxf(p3.x, 0.f) * sF[j + 6] + fmaxf(p3.y, 0.f) * sF[j + 7];
    }
    out[n] = o + bfc[0];
}

// ---------------- launch ----------------
extern "C" void kernel_launch(void* const* d_in, const int* in_sizes, int n_in,
                              void* d_out, int out_size) {
    const float* x   = (const float*)d_in[0];
    const void*  ei  = d_in[1];
    const float* W1  = (const float*)d_in[2];
    const float* b1  = (const float*)d_in[3];
    const float* W2  = (const float*)d_in[4];
    const float* b2  = (const float*)d_in[5];
    const float* W3  = (const float*)d_in[6];
    const float* b3  = (const float*)d_in[7];
    const float* Wfc = (const float*)d_in[8];
    const float* bfc = (const float*)d_in[9];
    float* out = (float*)d_out;

    const int TB = 256;
    const int gN = (N_NODES + TB - 1) / TB;
    const int gE = (N_EDGES + TB - 1) / TB;

    // graph construction
    k_init<<<gN, TB>>>((const unsigned int*)ei);
    k_count<<<gE, TB>>>(ei);
    k_scanA<<<SCAN_NB, SCAN_B>>>();
    k_scanB<<<1, 256>>>();
    k_scanC<<<gN, TB>>>();
    k_fill<<<gE, TB>>>(ei);

    // layer 1: GEMM first (128->16, pre-scaled), then aggregate 16-wide
    k_gemm1<<<gN, TB>>>(x, W1);
    k_aggv<16, 0><<<(N_NODES * 4 + TB - 1) / TB, TB>>>(b1);

    // layer 2: aggregate first (16-wide), then GEMM 16->64 (+bias+relu, pre-scaled)
    k_aggv<16, 1><<<(N_NODES * 4 + TB - 1) / TB, TB>>>(nullptr);
    k_gemm2<<<(N_NODES * 64 + TB - 1) / TB, TB>>>(W2, b2);

    // layer 3: aggregate first (64-wide), then fused GEMM 64->128 + relu + FC
    k_aggv<64, 2><<<(N_NODES * 16 + TB - 1) / TB, TB>>>(nullptr);
    k_final<<<gN, TB>>>(W3, b3, Wfc, bfc, out);
}

// round 5
// speedup vs baseline: 1.4046x; 1.0620x over previous
#include <cuda_runtime.h>
#include <cuda_fp16.h>

// Problem constants (fixed by setup_inputs)
static constexpr int N_NODES = 100000;
static constexpr int N_EDGES = 1600000;
static constexpr int SCAN_B  = 512;
static constexpr int SCAN_NB = (N_NODES + SCAN_B - 1) / SCAN_B;  // 196

// ---------------- scratch (static __device__, allocation-free) ----------------
__device__ int   g_cnt[N_NODES];        // degree counts, then CSR fill cursor
__device__ int   g_row[N_NODES + 1];    // CSR row offsets
__device__ int   g_blkagg[SCAN_NB];
__device__ volatile int g_blkflag[SCAN_NB];
__device__ int   g_col[N_EDGES];        // CSR: src node per entry
__device__ float g_dinv[N_NODES];
__device__ float g_t1[N_NODES * 16];    // dinv * (x @ W1)
__device__ float g_h1[N_NODES * 16];    // dinv * relu(...)   (pre-scaled)
__device__ float g_a2[N_NODES * 16];    // dinv * sum
__device__ unsigned int g_h2h[N_NODES * 32];  // fp16 half2: dinv * relu(a2@W2+b2)
__device__ float g_a3[N_NODES * 64];    // dinv * sum
__device__ int   g_is64;

// ---------------- f32x2 packed-FMA helpers (sm_103a) ----------------
typedef unsigned long long ull;
__device__ __forceinline__ ull pack2(float v) {
    ull r; asm("mov.b64 %0, {%1, %1};" : "=l"(r) : "f"(v)); return r;
}
__device__ __forceinline__ void ffma2(ull& d, ull a, ull b) {
    asm("fma.rn.f32x2 %0, %1, %2, %0;" : "+l"(d) : "l"(a), "l"(b));
}
__device__ __forceinline__ float2 unpack2(ull v) {
    float2 r; asm("mov.b64 {%0, %1}, %2;" : "=f"(r.x), "=f"(r.y) : "l"(v)); return r;
}

// ---------------- edge decode ----------------
__device__ __forceinline__ void edge_sd(const void* e, int idx, int& s, int& d) {
    if (g_is64) {
        const long long* p = (const long long*)e;
        s = (int)p[idx];
        d = (int)p[N_EDGES + idx];
    } else {
        const int* p = (const int*)e;
        s = p[idx];
        d = p[N_EDGES + idx];
    }
}

// ---------------- graph build ----------------
__global__ void k_init(const unsigned int* __restrict__ e) {
    int i = blockIdx.x * blockDim.x + threadIdx.x;
    if (i < N_NODES) g_cnt[i] = 0;
    if (i < SCAN_NB) g_blkflag[i] = 0;
    if (i == 0) {
        int is64 = 1;
        for (int k = 0; k < 64; k++) {
            if (e[2 * k + 1] != 0u) { is64 = 0; break; }
        }
        g_is64 = is64;
    }
}

__global__ void k_count(const void* e) {
    int i = blockIdx.x * blockDim.x + threadIdx.x;
    if (i >= N_EDGES) return;
    int d;
    if (g_is64) d = (int)((const long long*)e)[N_EDGES + i];
    else        d = ((const int*)e)[N_EDGES + i];
    if ((unsigned)d >= (unsigned)N_NODES) return;
    atomicAdd(&g_cnt[d], 1);
}

// single-kernel exclusive scan (aggregate publish + spin on earlier blocks).
// All 196 blocks are resident in wave 1 (196 < 148*occ), so spinning on
// earlier blocks' flags cannot deadlock. Also computes dinv and resets cursor.
__global__ void __launch_bounds__(SCAN_B) k_scan() {
    __shared__ int s[SCAN_B];
    __shared__ int sPre;
    int bid = blockIdx.x;
    int i = bid * SCAN_B + threadIdx.x;
    int v = (i < N_NODES) ? g_cnt[i] : 0;
    if (i < N_NODES) g_dinv[i] = rsqrtf((float)(v + 1));
    s[threadIdx.x] = v;
    __syncthreads();
    for (int d = 1; d < SCAN_B; d <<= 1) {
        int t = (threadIdx.x >= d) ? s[threadIdx.x - d] : 0;
        __syncthreads();
        s[threadIdx.x] += t;
        __syncthreads();
    }
    // publish this block's aggregate
    if (threadIdx.x == SCAN_B - 1) {
        g_blkagg[bid] = s[SCAN_B - 1];
        __threadfence();
        g_blkflag[bid] = 1;
    }
    if (threadIdx.x == 0) sPre = 0;
    __syncthreads();
    // sum aggregates of earlier blocks (spin until published)
    int p = 0;
    for (int b = threadIdx.x; b < bid; b += SCAN_B) {
        while (g_blkflag[b] == 0) { }
        p += *((volatile int*)&g_blkagg[b]);
    }
    if (p) atomicAdd(&sPre, p);
    __syncthreads();
    int prefix = sPre;
    if (i < N_NODES) {
        g_row[i] = prefix + s[threadIdx.x] - v;   // exclusive
        g_cnt[i] = 0;                              // reset as fill cursor
    }
    if (bid == 0 && threadIdx.x == 0) g_row[N_NODES] = N_EDGES;
}

__global__ void k_fill(const void* e) {
    int i = blockIdx.x * blockDim.x + threadIdx.x;
    if (i >= N_EDGES) return;
    int s, d;
    edge_sd(e, i, s, d);
    if ((unsigned)d >= (unsigned)N_NODES || (unsigned)s >= (unsigned)N_NODES) return;
    int pos = atomicAdd(&g_cnt[d], 1);
    int idx = g_row[d] + pos;
    if (idx < N_EDGES) g_col[idx] = s;
}

// ---------------- layer 1 GEMM: t1' = dinv ⊙ (x @ W1)  (f32x2) -----------------
__global__ void __launch_bounds__(256) k_gemm1(const float* __restrict__ x,
                                               const float* __restrict__ W1) {
    __shared__ __align__(16) float sW[128 * 16];
    for (int idx = threadIdx.x; idx < 128 * 16; idx += 256) sW[idx] = W1[idx];
    __syncthreads();
    int n = blockIdx.x * 256 + threadIdx.x;
    if (n >= N_NODES) return;
    const float4* xr = (const float4*)(x + (size_t)n * 128);
    ull acc[8];
#pragma unroll
    for (int q = 0; q < 8; q++) acc[q] = 0ull;
#pragma unroll 4
    for (int k4 = 0; k4 < 32; k4++) {
        float4 v = __ldg(&xr[k4]);
#pragma unroll
        for (int kk = 0; kk < 4; kk++) {
            float xv = (kk == 0) ? v.x : (kk == 1) ? v.y : (kk == 2) ? v.z : v.w;
            ull av = pack2(xv);
            const ulonglong2* wr = (const ulonglong2*)(sW + (4 * k4 + kk) * 16);
            ulonglong2 w01 = wr[0], w23 = wr[1], w45 = wr[2], w67 = wr[3];
            ffma2(acc[0], av, w01.x); ffma2(acc[1], av, w01.y);
            ffma2(acc[2], av, w23.x); ffma2(acc[3], av, w23.y);
            ffma2(acc[4], av, w45.x); ffma2(acc[5], av, w45.y);
            ffma2(acc[6], av, w67.x); ffma2(acc[7], av, w67.y);
        }
    }
    float di = g_dinv[n];
    float4* o = (float4*)(g_t1 + (size_t)n * 16);
#pragma unroll
    for (int q = 0; q < 4; q++) {
        float2 p0 = unpack2(acc[2 * q]), p1 = unpack2(acc[2 * q + 1]);
        o[q] = make_float4(di * p0.x, di * p0.y, di * p1.x, di * p1.y);
    }
}

// ---------------- fp32 aggregation (16-wide), inputs pre-scaled by dinv --------
// SEL 0: h1' = relu(di²·S + di·b1)   SEL 1: a2 = di·S
template <int SEL>
__global__ void __launch_bounds__(256) k_agg16(const float* __restrict__ bias) {
    const float4* __restrict__ t4 = (SEL == 0) ? (const float4*)g_t1 : (const float4*)g_h1;
    float4* __restrict__ o4       = (SEL == 0) ? (float4*)g_h1       : (float4*)g_a2;
    int g = threadIdx.x & 3;
    int i = blockIdx.x * 64 + (threadIdx.x >> 2);
    if (i >= N_NODES) return;

    float4 acc = t4[(size_t)i * 4 + g];  // self loop
    int beg = g_row[i], end = g_row[i + 1];
    int j = beg;
    for (; j + 3 < end; j += 4) {
        int s0 = __ldg(&g_col[j]);
        int s1 = __ldg(&g_col[j + 1]);
        int s2 = __ldg(&g_col[j + 2]);
        int s3 = __ldg(&g_col[j + 3]);
        float4 v0 = __ldg(&t4[(size_t)s0 * 4 + g]);
        float4 v1 = __ldg(&t4[(size_t)s1 * 4 + g]);
        float4 v2 = __ldg(&t4[(size_t)s2 * 4 + g]);
        float4 v3 = __ldg(&t4[(size_t)s3 * 4 + g]);
        acc.x += (v0.x + v1.x) + (v2.x + v3.x);
        acc.y += (v0.y + v1.y) + (v2.y + v3.y);
        acc.z += (v0.z + v1.z) + (v2.z + v3.z);
        acc.w += (v0.w + v1.w) + (v2.w + v3.w);
    }
    for (; j < end; j++) {
        int s = __ldg(&g_col[j]);
        float4 v = __ldg(&t4[(size_t)s * 4 + g]);
        acc.x += v.x; acc.y += v.y; acc.z += v.z; acc.w += v.w;
    }
    float di = g_dinv[i];
    float4 r;
    if (SEL == 0) {
        float4 b = ((const float4*)bias)[g];
        float d2 = di * di;
        r.x = fmaxf(fmaf(d2, acc.x, di * b.x), 0.f);
        r.y = fmaxf(fmaf(d2, acc.y, di * b.y), 0.f);
        r.z = fmaxf(fmaf(d2, acc.z, di * b.z), 0.f);
        r.w = fmaxf(fmaf(d2, acc.w, di * b.w), 0.f);
    } else {
        r = make_float4(di * acc.x, di * acc.y, di * acc.z, di * acc.w);
    }
    o4[(size_t)i * 4 + g] = r;
}

// ---------------- layer 2 GEMM: h2' = fp16( dinv ⊙ relu(a2@W2+b2) )  (f32x2) ---
// warp-per-node: lane = output feature-pair, a2 row loads fully broadcast.
__global__ void __launch_bounds__(256) k_gemm2(const float* __restrict__ W2,
                                               const float* __restrict__ b2) {
    __shared__ __align__(16) float sW[16 * 64];
    __shared__ __align__(16) float sB[64];
    for (int idx = threadIdx.x; idx < 16 * 64; idx += 256) sW[idx] = W2[idx];
    if (threadIdx.x < 64) sB[threadIdx.x] = b2[threadIdx.x];
    __syncthreads();
    int tid = blockIdx.x * 256 + threadIdx.x;
    if (tid >= N_NODES * 32) return;
    int n = tid >> 5;          // all 32 lanes of a warp share one node
    int f2 = tid & 31;         // output pair index (2 features)
    const float4* ar = (const float4*)(g_a2 + (size_t)n * 16);
    ull acc = ((const ull*)sB)[f2];
#pragma unroll
    for (int k4 = 0; k4 < 4; k4++) {
        float4 v = __ldg(&ar[k4]);   // broadcast across warp
#pragma unroll
        for (int kk = 0; kk < 4; kk++) {
            float av = (kk == 0) ? v.x : (kk == 1) ? v.y : (kk == 2) ? v.z : v.w;
            ffma2(acc, pack2(av), ((const ull*)sW)[(4 * k4 + kk) * 32 + f2]);
        }
    }
    float di = g_dinv[n];
    float2 p = unpack2(acc);
    __half2 h = __floats2half2_rn(fmaxf(di * p.x, 0.f), fmaxf(di * p.y, 0.f));
    g_h2h[tid] = *(const unsigned int*)&h;
}

// ---------------- fp16 aggregation (64-wide): a3 = di·(h2'[i] + Σ h2'[src]) ----
__global__ void __launch_bounds__(256) k_agg64h() {
    const uint2* __restrict__ t = (const uint2*)g_h2h;  // 16 uint2 (=4 halves ea) per node
    int g = threadIdx.x & 15;
    int i = blockIdx.x * 16 + (threadIdx.x >> 4);
    if (i >= N_NODES) return;

    uint2 sv = __ldg(&t[(size_t)i * 16 + g]);
    float2 lo = __half22float2(*(const __half2*)&sv.x);
    float2 hi = __half22float2(*(const __half2*)&sv.y);
    float4 acc = make_float4(lo.x, lo.y, hi.x, hi.y);

    int beg = g_row[i], end = g_row[i + 1];
    int j = beg;
    for (; j + 3 < end; j += 4) {
        int s0 = __ldg(&g_col[j]);
        int s1 = __ldg(&g_col[j + 1]);
        int s2 = __ldg(&g_col[j + 2]);
        int s3 = __ldg(&g_col[j + 3]);
        uint2 v0 = __ldg(&t[(size_t)s0 * 16 + g]);
        uint2 v1 = __ldg(&t[(size_t)s1 * 16 + g]);
        uint2 v2 = __ldg(&t[(size_t)s2 * 16 + g]);
        uint2 v3 = __ldg(&t[(size_t)s3 * 16 + g]);
        float2 a0 = __half22float2(*(const __half2*)&v0.x), b0 = __half22float2(*(const __half2*)&v0.y);
        float2 a1 = __half22float2(*(const __half2*)&v1.x), b1 = __half22float2(*(const __half2*)&v1.y);
        float2 a2 = __half22float2(*(const __half2*)&v2.x), b2 = __half22float2(*(const __half2*)&v2.y);
        float2 a3 = __half22float2(*(const __half2*)&v3.x), b3 = __half22float2(*(const __half2*)&v3.y);
        acc.x += (a0.x + a1.x) + (a2.x + a3.x);
        acc.y += (a0.y + a1.y) + (a2.y + a3.y);
        acc.z += (b0.x + b1.x) + (b2.x + b3.x);
        acc.w += (b0.y + b1.y) + (b2.y + b3.y);
    }
    for (; j < end; j++) {
        int s = __ldg(&g_col[j]);
        uint2 v = __ldg(&t[(size_t)s * 16 + g]);
        float2 a = __half22float2(*(const __half2*)&v.x);
        float2 b = __half22float2(*(const __half2*)&v.y);
        acc.x += a.x; acc.y += a.y; acc.z += b.x; acc.w += b.y;
    }
    float di = g_dinv[i];
    ((float4*)g_a3)[(size_t)i * 16 + g] =
        make_float4(di * acc.x, di * acc.y, di * acc.z, di * acc.w);
}

// ---------------- fused layer 3 + FC (f32x2):
// out[n] = Σ_j relu( a3[n,:]·W3[:,j] + b3[j] ) * Wfc[j] + bfc
__global__ void __launch_bounds__(256) k_final(const float* __restrict__ W3,
                                               const float* __restrict__ b3,
                                               const float* __restrict__ Wfc,
                                               const float* __restrict__ bfc,
                                               float* __restrict__ out) {
    __shared__ __align__(16) float sW[64 * 128];   // 32KB
    __shared__ __align__(16) float sB[128];
    __shared__ __align__(16) float sF[128];
    for (int idx = threadIdx.x; idx < 64 * 128; idx += 256) sW[idx] = W3[idx];
    if (threadIdx.x < 128) {
        sB[threadIdx.x] = b3[threadIdx.x];
        sF[threadIdx.x] = Wfc[threadIdx.x];
    }
    __syncthreads();
    int n = blockIdx.x * 256 + threadIdx.x;
    if (n >= N_NODES) return;

    float a[64];
    const float4* ar = (const float4*)(g_a3 + (size_t)n * 64);
#pragma unroll
    for (int k4 = 0; k4 < 16; k4++) {
        float4 v = __ldg(&ar[k4]);
        a[4 * k4 + 0] = v.x; a[4 * k4 + 1] = v.y;
        a[4 * k4 + 2] = v.z; a[4 * k4 + 3] = v.w;
    }

    float o = 0.f;
#pragma unroll 1
    for (int j = 0; j < 128; j += 8) {
        const ulonglong2* bi = (const ulonglong2*)(sB + j);
        ulonglong2 b01 = bi[0], b23 = bi[1];
        ull acc0 = b01.x, acc1 = b01.y, acc2 = b23.x, acc3 = b23.y;
#pragma unroll
        for (int k = 0; k < 64; k++) {
            ull av = pack2(a[k]);
            const ulonglong2* w = (const ulonglong2*)(sW + k * 128 + j);
            ulonglong2 w01 = w[0], w23 = w[1];
            ffma2(acc0, av, w01.x);
            ffma2(acc1, av, w01.y);
            ffma2(acc2, av, w23.x);
            ffma2(acc3, av, w23.y);
        }
        float2 p0 = unpack2(acc0), p1 = unpack2(acc1);
        float2 p2 = unpack2(acc2), p3 = unpack2(acc3);
        o += fmaxf(p0.x, 0.f) * sF[j + 0] + fmaxf(p0.y, 0.f) * sF[j + 1];
        o += fmaxf(p1.x, 0.f) * sF[j + 2] + fmaxf(p1.y, 0.f) * sF[j + 3];
        o += fmaxf(p2.x, 0.f) * sF[j + 4] + fmaxf(p2.y, 0.f) * sF[j + 5];
        o += fmaxf(p3.x, 0.f) * sF[j + 6] + fmaxf(p3.y, 0.f) * sF[j + 7];
    }
    out[n] = o + bfc[0];
}

// ---------------- launch ----------------
extern "C" void kernel_launch(void* const* d_in, const int* in_sizes, int n_in,
                              void* d_out, int out_size) {
    const float* x   = (const float*)d_in[0];
    const void*  ei  = d_in[1];
    const float* W1  = (const float*)d_in[2];
    const float* b1  = (const float*)d_in[3];
    const float* W2  = (const float*)d_in[4];
    const float* b2  = (const float*)d_in[5];
    const float* W3  = (const float*)d_in[6];
    const float* b3  = (const float*)d_in[7];
    const float* Wfc = (const float*)d_in[8];
    const float* bfc = (const float*)d_in[9];
    float* out = (float*)d_out;

    const int TB = 256;
    const int gN = (N_NODES + TB - 1) / TB;
    const int gE = (N_EDGES + TB - 1) / TB;

    // graph construction (count -> one-kernel scan -> fill)
    k_init<<<gN, TB>>>((const unsigned int*)ei);
    k_count<<<gE, TB>>>(ei);
    k_scan<<<SCAN_NB, SCAN_B>>>();
    k_fill<<<gE, TB>>>(ei);

    // layer 1: GEMM (128->16, pre-scaled) then aggregate 16-wide (+b1+relu)
    k_gemm1<<<gN, TB>>>(x, W1);
    k_agg16<0><<<(N_NODES * 4 + TB - 1) / TB, TB>>>(b1);

    // layer 2: aggregate 16-wide, then GEMM 16->64 -> fp16 h2'
    k_agg16<1><<<(N_NODES * 4 + TB - 1) / TB, TB>>>(nullptr);
    k_gemm2<<<(N_NODES * 32 + TB - 1) / TB, TB>>>(W2, b2);

    // layer 3: fp16 aggregate 64-wide, then fused GEMM 64->128 + relu + FC
    k_agg64h<<<(N_NODES * 16 + TB - 1) / TB, TB>>>();
    k_final<<<gN, TB>>>(W3, b3, Wfc, bfc, out);
}